// round 4
// baseline (speedup 1.0000x reference)
#include <cuda_runtime.h>
#include <math.h>

#define N_NODES 50000
#define E_EDGES 640000
#define HID 128
#define NG 50
#define NGRAPHS 64
#define NBATCH 8          // edges per batch in edge kernel

// ---------------- scratch (static device globals; no allocs allowed) ---------
__device__ __align__(16) float g_ea[(size_t)E_EDGES * NG];   // envelope-folded gaussians
__device__ __align__(16) float g_C[E_EDGES];                 // cosine cutoff
__device__ __align__(16) int   g_src[E_EDGES];
__device__ __align__(16) int   g_dst[E_EDGES];
__device__ __align__(16) float g_h[(size_t)N_NODES * HID];
__device__ __align__(16) float g_xf[(size_t)N_NODES * HID];
__device__ __align__(16) float g_agg[(size_t)N_NODES * HID];
__device__ int g_is64;

typedef unsigned long long u64;

__device__ __forceinline__ u64 pack2(float x, float y) {
    u64 r; asm("mov.b64 %0,{%1,%2};" : "=l"(r) : "f"(x), "f"(y)); return r;
}
__device__ __forceinline__ float2 unpack2(u64 v) {
    float2 f; asm("mov.b64 {%0,%1},%2;" : "=f"(f.x), "=f"(f.y) : "l"(v)); return f;
}
#define FMA2(d, a, b, c) asm("fma.rn.f32x2 %0,%1,%2,%3;" : "=l"(d) : "l"(a), "l"(b), "l"(c))

__device__ __forceinline__ float sspf(float x) {
    // shifted softplus: log(1+e^x) - log(2), numerically stable
    float ax = fabsf(x);
    float sp = log1pf(__expf(-ax));
    return (x > 0.f ? x + sp : sp) - 0.6931471805599453f;
}

// ---------------- dtype sniffer for edge_index -------------------------------
// If edge_index is int64 (little-endian, values < 2^31), odd 32-bit words are 0.
// If int32, odd words are random node ids (nonzero w.p. ~1).
__global__ void detect_kernel(const int* __restrict__ ei) {
    if (threadIdx.x == 0 && blockIdx.x == 0) {
        int acc = ei[1] | ei[3] | ei[5] | ei[7] | ei[9] | ei[11] | ei[13] | ei[15];
        g_is64 = (acc == 0) ? 1 : 0;
    }
}

// ---------------- prep: per-edge geometry + gaussians ------------------------
__global__ void prep_kernel(const int* __restrict__ ei, const float* __restrict__ pos) {
    int e = blockIdx.x * blockDim.x + threadIdx.x;
    if (e >= E_EDGES) return;
    int s, t;
    if (g_is64) {
        const long long* ei64 = (const long long*)ei;
        s = (int)ei64[e];
        t = (int)ei64[E_EDGES + e];
    } else {
        s = ei[e];
        t = ei[E_EDGES + e];
    }
    float dx = pos[t * 3 + 0] - pos[s * 3 + 0];
    float dy = pos[t * 3 + 1] - pos[s * 3 + 1];
    float dz = pos[t * 3 + 2] - pos[s * 3 + 2];
    float d = sqrtf(dx * dx + dy * dy + dz * dz);
    g_src[e] = s;
    g_dst[e] = t;
    g_C[e] = 0.5f * (cosf(d * 0.62831853071795864f) + 1.0f);  // pi/5
    float srel = d * 0.2f;
    float env = 0.f;
    if (srel < 1.f) {
        float dn = 1.f - srel * srel;
        env = expf(1.f - 1.f / dn);
    }
    const float step = 5.0f / 49.0f;
    const float coeff = -0.5f / (step * step);
    #pragma unroll 5
    for (int k = 0; k < NG; k++) {
        float off = step * (float)k;
        float dd = d - off;
        g_ea[(size_t)e * NG + k] = expf(coeff * dd * dd) * env;
    }
}

// ---------------- embedding gather -------------------------------------------
__global__ void embed_kernel(const int* __restrict__ z, const float* __restrict__ emb) {
    int i = blockIdx.x * blockDim.x + threadIdx.x;
    if (i >= N_NODES * HID) return;
    int n = i >> 7, c = i & 127;
    g_h[i] = emb[z[n] * HID + c];
}

// ---------------- node GEMM: [N,128] @ [128,128] with epilogue modes ---------
// MODE 0: C = A@W
// MODE 1: C = ssp(A@W + b)
// MODE 2: C = C + A@W + b   (residual accumulate into Cout)
template <int MODE>
__global__ __launch_bounds__(256) void node_gemm(const float* __restrict__ A,
                                                 const float* __restrict__ W,
                                                 const float* __restrict__ bias,
                                                 float* __restrict__ Cout) {
    extern __shared__ float sm[];
    float* As = sm;               // [128][128] As[r][k]
    float* Ws = sm + 128 * 128;   // [128][128] Ws[k][c]
    int tid = threadIdx.x;
    int row0 = blockIdx.x * 128;
    for (int i = tid; i < 128 * 128; i += 256) {
        int r = i >> 7;
        As[i] = (row0 + r < N_NODES) ? A[(size_t)(row0 + r) * 128 + (i & 127)] : 0.f;
        Ws[i] = W[i];
    }
    __syncthreads();
    int tx = tid & 15, ty = tid >> 4;
    u64 acc[8][4];
    #pragma unroll
    for (int i = 0; i < 8; i++)
        #pragma unroll
        for (int p = 0; p < 4; p++) acc[i][p] = 0ull;

    #pragma unroll 4
    for (int k = 0; k < 128; k++) {
        ulonglong2 b0 = *(const ulonglong2*)&Ws[k * 128 + tx * 8];
        ulonglong2 b1 = *(const ulonglong2*)&Ws[k * 128 + tx * 8 + 4];
        #pragma unroll
        for (int i = 0; i < 8; i++) {
            float a = As[(ty * 8 + i) * 128 + k];
            u64 ad = pack2(a, a);
            FMA2(acc[i][0], ad, b0.x, acc[i][0]);
            FMA2(acc[i][1], ad, b0.y, acc[i][1]);
            FMA2(acc[i][2], ad, b1.x, acc[i][2]);
            FMA2(acc[i][3], ad, b1.y, acc[i][3]);
        }
    }
    int c0 = tx * 8;
    #pragma unroll
    for (int i = 0; i < 8; i++) {
        int row = row0 + ty * 8 + i;
        if (row < N_NODES) {
            float o[8];
            #pragma unroll
            for (int p = 0; p < 4; p++) {
                float2 f = unpack2(acc[i][p]);
                o[2 * p] = f.x;
                o[2 * p + 1] = f.y;
            }
            float* dst = &Cout[(size_t)row * 128 + c0];
            if (MODE == 0) {
                #pragma unroll
                for (int j = 0; j < 8; j++) dst[j] = o[j];
            } else if (MODE == 1) {
                #pragma unroll
                for (int j = 0; j < 8; j++) dst[j] = sspf(o[j] + bias[c0 + j]);
            } else {
                #pragma unroll
                for (int j = 0; j < 8; j++) dst[j] = dst[j] + o[j] + bias[c0 + j];
            }
        }
    }
}

// ---------------- fused edge MLP + modulate + scatter ------------------------
// block = 128 threads (thread j owns output dim j), NBATCH=8 edges per iter.
// f32x2: edges packed in pairs, weights duplicated into both halves.
__global__ __launch_bounds__(128) void edge_kernel(const float* __restrict__ w1,
                                                   const float* __restrict__ b1,
                                                   const float* __restrict__ w2,
                                                   const float* __restrict__ b2) {
    extern __shared__ char smemc[];
    float* w2s  = (float*)smemc;                  // 128*128
    float* eas  = w2s + 128 * 128;                // [50][8]  (k*8 + u), pairs adjacent
    float* tss  = eas + NG * NBATCH;              // [128][8]
    float* msgb = tss + 128 * NBATCH;             // [8][128]
    int*   srcs = (int*)(msgb + NBATCH * 128);    // 8
    int*   dsts = srcs + NBATCH;                  // 8
    float* Cs   = (float*)(dsts + NBATCH);        // 8

    int tid = threadIdx.x;

    // per-thread weight column of w1 in registers
    float w1col[NG];
    #pragma unroll
    for (int k = 0; k < NG; k++) w1col[k] = w1[k * 128 + tid];
    float b1r = b1[tid];
    float b2r = b2[tid];
    for (int i = tid; i < 128 * 128; i += 128) w2s[i] = w2[i];
    __syncthreads();

    const int nb = E_EDGES / NBATCH;
    for (int b = blockIdx.x; b < nb; b += gridDim.x) {
        int base = b * NBATCH;
        if (tid < NBATCH) {
            int e = base + tid;
            srcs[tid] = g_src[e];
            dsts[tid] = g_dst[e];
            Cs[tid] = g_C[e];
        }
        for (int i = tid; i < NG * NBATCH; i += 128) {
            int u = i / NG, k = i - u * NG;
            eas[k * NBATCH + u] = g_ea[(size_t)(base + u) * NG + k];
        }
        __syncthreads();

        // phase 1: t = ea @ w1 + b1  (per output dim tid, 8 edges as 4 f32x2)
        u64 a0 = pack2(b1r, b1r), a1 = a0, a2 = a0, a3 = a0;
        #pragma unroll
        for (int k = 0; k < NG; k++) {
            u64 wd = pack2(w1col[k], w1col[k]);
            ulonglong2 e0 = *(const ulonglong2*)&eas[k * NBATCH];
            ulonglong2 e1 = *(const ulonglong2*)&eas[k * NBATCH + 4];
            FMA2(a0, e0.x, wd, a0);
            FMA2(a1, e0.y, wd, a1);
            FMA2(a2, e1.x, wd, a2);
            FMA2(a3, e1.y, wd, a3);
        }
        {
            float2 f0 = unpack2(a0), f1 = unpack2(a1), f2 = unpack2(a2), f3 = unpack2(a3);
            float* tr = &tss[tid * NBATCH];
            tr[0] = sspf(f0.x); tr[1] = sspf(f0.y);
            tr[2] = sspf(f1.x); tr[3] = sspf(f1.y);
            tr[4] = sspf(f2.x); tr[5] = sspf(f2.y);
            tr[6] = sspf(f3.x); tr[7] = sspf(f3.y);
        }
        __syncthreads();

        // phase 2: W = ssp(t) @ w2 + b2
        a0 = pack2(b2r, b2r); a1 = a0; a2 = a0; a3 = a0;
        #pragma unroll 4
        for (int k = 0; k < 128; k++) {
            float w = w2s[k * 128 + tid];
            u64 wd = pack2(w, w);
            ulonglong2 t0 = *(const ulonglong2*)&tss[k * NBATCH];
            ulonglong2 t1 = *(const ulonglong2*)&tss[k * NBATCH + 4];
            FMA2(a0, t0.x, wd, a0);
            FMA2(a1, t0.y, wd, a1);
            FMA2(a2, t1.x, wd, a2);
            FMA2(a3, t1.y, wd, a3);
        }

        // epilogue: msg = W * C * xf[src]
        {
            float2 f0 = unpack2(a0), f1 = unpack2(a1), f2 = unpack2(a2), f3 = unpack2(a3);
            msgb[0 * 128 + tid] = f0.x * Cs[0] * g_xf[(size_t)srcs[0] * 128 + tid];
            msgb[1 * 128 + tid] = f0.y * Cs[1] * g_xf[(size_t)srcs[1] * 128 + tid];
            msgb[2 * 128 + tid] = f1.x * Cs[2] * g_xf[(size_t)srcs[2] * 128 + tid];
            msgb[3 * 128 + tid] = f1.y * Cs[3] * g_xf[(size_t)srcs[3] * 128 + tid];
            msgb[4 * 128 + tid] = f2.x * Cs[4] * g_xf[(size_t)srcs[4] * 128 + tid];
            msgb[5 * 128 + tid] = f2.y * Cs[5] * g_xf[(size_t)srcs[5] * 128 + tid];
            msgb[6 * 128 + tid] = f3.x * Cs[6] * g_xf[(size_t)srcs[6] * 128 + tid];
            msgb[7 * 128 + tid] = f3.y * Cs[7] * g_xf[(size_t)srcs[7] * 128 + tid];
        }
        __syncthreads();

        // vectorized scatter-add: 8 edges * 128 floats = 256 float4 reductions
        #pragma unroll
        for (int r = 0; r < 2; r++) {
            int q = r * 128 + tid;
            int u = q >> 5;
            int c4 = (q & 31) * 4;
            float4 v = *(const float4*)&msgb[u * 128 + c4];
            float* p = &g_agg[(size_t)dsts[u] * 128 + c4];
            asm volatile("red.global.add.v4.f32 [%0], {%1,%2,%3,%4};"
                         :: "l"(p), "f"(v.x), "f"(v.y), "f"(v.z), "f"(v.w)
                         : "memory");
        }
        __syncthreads();
    }
}

// ---------------- readout: ssp(h@out1+b1)@out2 + b2 -> segment sum -----------
__global__ __launch_bounds__(128) void readout_kernel(const float* __restrict__ w1,
                                                      const float* __restrict__ b1,
                                                      const float* __restrict__ w2,
                                                      const float* __restrict__ b2v,
                                                      const int* __restrict__ batch,
                                                      float* __restrict__ out) {
    __shared__ float w1s[128 * 64];
    __shared__ float w2s2[64];
    __shared__ float hs[2][128];
    __shared__ float red[2][64];
    int tid = threadIdx.x;
    for (int i = tid; i < 128 * 64; i += 128) w1s[i] = w1[i];
    if (tid < 64) w2s2[tid] = w2[tid];
    __syncthreads();

    int half = tid >> 6;     // which of the 2 nodes this thread works on
    int c = tid & 63;        // output column of the hidden layer
    float b1r = b1[c];
    float b2r = b2v[0];

    const int npairs = N_NODES / 2;
    for (int pair = blockIdx.x; pair < npairs; pair += gridDim.x) {
        for (int i = tid; i < 256; i += 128) {
            int nd = pair * 2 + (i >> 7);
            hs[i >> 7][i & 127] = g_h[(size_t)nd * 128 + (i & 127)];
        }
        __syncthreads();
        float acc = b1r;
        #pragma unroll 4
        for (int k = 0; k < 128; k++) acc += hs[half][k] * w1s[k * 64 + c];
        float h2 = sspf(acc);
        red[half][c] = h2 * w2s2[c];
        __syncthreads();
        if (c < 32) {
            float v = red[half][c] + red[half][c + 32];
            #pragma unroll
            for (int off = 16; off >= 1; off >>= 1)
                v += __shfl_down_sync(0xffffffffu, v, off);
            if (c == 0) {
                int node = pair * 2 + half;
                atomicAdd(&out[batch[node]], v + b2r);
            }
        }
        __syncthreads();
    }
}

// ---------------- launch ------------------------------------------------------
extern "C" void kernel_launch(void* const* d_in, const int* in_sizes, int n_in,
                              void* d_out, int out_size) {
    const int*       z       = (const int*)d_in[0];
    const float*     pos     = (const float*)d_in[1];
    const int*       ei      = (const int*)d_in[2];   // int32 or int64 (sniffed on device)
    const int*       batch   = (const int*)d_in[3];
    const float*     emb     = (const float*)d_in[4];
    const float*     mlp_w1  = (const float*)d_in[5];
    const float*     mlp_b1  = (const float*)d_in[6];
    const float*     mlp_w2  = (const float*)d_in[7];
    const float*     mlp_b2  = (const float*)d_in[8];
    const float*     conv1_w = (const float*)d_in[9];
    const float*     conv2_w = (const float*)d_in[10];
    const float*     conv2_b = (const float*)d_in[11];
    const float*     lin_w   = (const float*)d_in[12];
    const float*     lin_b   = (const float*)d_in[13];
    const float*     out1_w  = (const float*)d_in[14];
    const float*     out1_b  = (const float*)d_in[15];
    const float*     out2_w  = (const float*)d_in[16];
    const float*     out2_b  = (const float*)d_in[17];

    const int GEMM_SMEM = 2 * 128 * 128 * 4;  // 131072
    const int EDGE_SMEM = (128 * 128 + NG * NBATCH + 128 * NBATCH + NBATCH * 128) * 4
                          + NBATCH * 4 * 3;   // w2s + eas + tss + msgb + meta

    cudaFuncSetAttribute(node_gemm<0>, cudaFuncAttributeMaxDynamicSharedMemorySize, GEMM_SMEM);
    cudaFuncSetAttribute(node_gemm<1>, cudaFuncAttributeMaxDynamicSharedMemorySize, GEMM_SMEM);
    cudaFuncSetAttribute(node_gemm<2>, cudaFuncAttributeMaxDynamicSharedMemorySize, GEMM_SMEM);
    cudaFuncSetAttribute(edge_kernel, cudaFuncAttributeMaxDynamicSharedMemorySize, EDGE_SMEM);

    float *hP, *xfP, *aggP;
    cudaGetSymbolAddress((void**)&hP, g_h);
    cudaGetSymbolAddress((void**)&xfP, g_xf);
    cudaGetSymbolAddress((void**)&aggP, g_agg);

    detect_kernel<<<1, 32>>>(ei);
    prep_kernel<<<(E_EDGES + 255) / 256, 256>>>(ei, pos);
    embed_kernel<<<(N_NODES * HID + 255) / 256, 256>>>(z, emb);

    const int gemm_grid = (N_NODES + 127) / 128;  // 391
    for (int l = 0; l < 3; l++) {
        node_gemm<0><<<gemm_grid, 256, GEMM_SMEM>>>(hP, conv1_w + (size_t)l * 128 * 128, nullptr, xfP);
        cudaMemsetAsync(aggP, 0, (size_t)N_NODES * 128 * sizeof(float));
        edge_kernel<<<444, 128, EDGE_SMEM>>>(mlp_w1 + (size_t)l * NG * 128,
                                             mlp_b1 + (size_t)l * 128,
                                             mlp_w2 + (size_t)l * 128 * 128,
                                             mlp_b2 + (size_t)l * 128);
        node_gemm<1><<<gemm_grid, 256, GEMM_SMEM>>>(aggP, conv2_w + (size_t)l * 128 * 128,
                                                    conv2_b + (size_t)l * 128, xfP);
        node_gemm<2><<<gemm_grid, 256, GEMM_SMEM>>>(xfP, lin_w + (size_t)l * 128 * 128,
                                                    lin_b + (size_t)l * 128, hP);
    }

    cudaMemsetAsync(d_out, 0, NGRAPHS * sizeof(float));
    readout_kernel<<<1024, 128>>>(out1_w, out1_b, out2_w, out2_b, batch, (float*)d_out);
}

// round 6
// speedup vs baseline: 1.3343x; 1.3343x over previous
#include <cuda_runtime.h>
#include <math.h>

#define N_NODES 50000
#define E_EDGES 640000
#define NG 50
#define NGRAPHS 64

typedef unsigned int u32;

// ---------------- scratch ----------------------------------------------------
__device__ __align__(16) float g_d[E_EDGES];
__device__ __align__(16) float g_C[E_EDGES];
__device__ __align__(16) int   g_src[E_EDGES];
__device__ __align__(16) int   g_dst[E_EDGES];
__device__ __align__(16) float g_h[(size_t)N_NODES * 128];
__device__ __align__(16) float g_xf[(size_t)N_NODES * 128];
__device__ __align__(16) float g_agg[(size_t)N_NODES * 128];
__device__ int g_is64;

// ---------------- helpers -----------------------------------------------------
__device__ __forceinline__ u32 f2tf(float f) {
    u32 r; asm("cvt.rna.tf32.f32 %0,%1;" : "=r"(r) : "f"(f)); return r;
}
__device__ __forceinline__ void mma8(float& c0, float& c1, float& c2, float& c3,
                                     u32 a0, u32 a1, u32 a2, u32 a3, u32 b0, u32 b1) {
    asm("mma.sync.aligned.m16n8k8.row.col.f32.tf32.tf32.f32 "
        "{%0,%1,%2,%3},{%4,%5,%6,%7},{%8,%9},{%0,%1,%2,%3};"
        : "+f"(c0), "+f"(c1), "+f"(c2), "+f"(c3)
        : "r"(a0), "r"(a1), "r"(a2), "r"(a3), "r"(b0), "r"(b1));
}
__device__ __forceinline__ float ex2f(float x) { float r; asm("ex2.approx.ftz.f32 %0,%1;" : "=f"(r) : "f"(x)); return r; }
__device__ __forceinline__ float lg2f_(float x) { float r; asm("lg2.approx.ftz.f32 %0,%1;" : "=f"(r) : "f"(x)); return r; }
__device__ __forceinline__ float ssp_fast(float x) {
    float e = ex2f(x * 1.4426950408889634f);
    return 0.6931471805599453f * (lg2f_(1.0f + e) - 1.0f);
}
__device__ __forceinline__ float sspf(float x) {
    float ax = fabsf(x);
    float sp = log1pf(__expf(-ax));
    return (x > 0.f ? x + sp : sp) - 0.6931471805599453f;
}
__device__ __forceinline__ void redf(float* p, float v) {
    asm volatile("red.global.add.f32 [%0], %1;" :: "l"(p), "f"(v) : "memory");
}

// ---------------- small kernels ----------------------------------------------
__global__ void detect_kernel(const int* __restrict__ ei) {
    if (threadIdx.x == 0 && blockIdx.x == 0) {
        int acc = ei[1] | ei[3] | ei[5] | ei[7] | ei[9] | ei[11] | ei[13] | ei[15];
        g_is64 = (acc == 0) ? 1 : 0;
    }
}
__global__ void prep_kernel(const int* __restrict__ ei, const float* __restrict__ pos) {
    int e = blockIdx.x * blockDim.x + threadIdx.x;
    if (e >= E_EDGES) return;
    int s, t;
    if (g_is64) { const long long* q = (const long long*)ei; s = (int)q[e]; t = (int)q[E_EDGES + e]; }
    else { s = ei[e]; t = ei[E_EDGES + e]; }
    float dx = pos[t * 3 + 0] - pos[s * 3 + 0];
    float dy = pos[t * 3 + 1] - pos[s * 3 + 1];
    float dz = pos[t * 3 + 2] - pos[s * 3 + 2];
    float d = sqrtf(dx * dx + dy * dy + dz * dz);
    g_src[e] = s; g_dst[e] = t; g_d[e] = d;
    g_C[e] = 0.5f * (cosf(d * 0.62831853071795864f) + 1.0f);
}
__global__ void embed_kernel(const int* __restrict__ z, const float* __restrict__ emb) {
    int i = blockIdx.x * blockDim.x + threadIdx.x;
    if (i >= N_NODES * 128) return;
    g_h[i] = emb[z[i >> 7] * 128 + (i & 127)];
}

// ---------------- warp-MMA node GEMM: [128 tile,128]@[128,128] ----------------
// MODE 0: C=A@W ; 1: C=ssp(A@W+b) ; 2: C+=A@W+b
#define SA 132   // padded stride for 128-wide tiles
template <int MODE>
__global__ __launch_bounds__(128) void mm_gemm(const float* __restrict__ A,
                                               const float* __restrict__ W,
                                               const float* __restrict__ bias,
                                               float* __restrict__ Cout) {
    extern __shared__ u32 sm[];
    u32* As = sm;                 // [128][SA] tf32
    u32* Bs = sm + 128 * SA;      // [128][SA] tf32  (Bs[k][n] = W[k][n])
    float* bsm = (float*)(Bs + 128 * SA);
    int tid = threadIdx.x, lane = tid & 31, w = tid >> 5;
    int row0 = blockIdx.x * 128;

    for (int i = tid; i < 16384; i += 128) {
        int r = i >> 7, k = i & 127;
        float v = (row0 + r < N_NODES) ? A[(size_t)(row0 + r) * 128 + k] : 0.f;
        As[r * SA + k] = f2tf(v);
        Bs[r * SA + k] = f2tf(W[i]);      // r:=k, k:=n
    }
    if (MODE != 0) bsm[tid] = bias[tid];
    __syncthreads();

    int g = lane >> 2, t4 = lane & 3;
    int n0 = w * 32;
    float c[8][4][4];
    #pragma unroll
    for (int m = 0; m < 8; m++)
        #pragma unroll
        for (int n = 0; n < 4; n++)
            #pragma unroll
            for (int q = 0; q < 4; q++) c[m][n][q] = 0.f;

    #pragma unroll
    for (int kk = 0; kk < 16; kk++) {
        int kb = kk * 8 + t4;
        u32 b[4][2];
        #pragma unroll
        for (int n = 0; n < 4; n++) {
            int col = n0 + n * 8 + g;
            b[n][0] = Bs[kb * SA + col];
            b[n][1] = Bs[(kb + 4) * SA + col];
        }
        #pragma unroll
        for (int m = 0; m < 8; m++) {
            int r = m * 16 + g;
            u32 a0 = As[r * SA + kb], a1 = As[(r + 8) * SA + kb];
            u32 a2 = As[r * SA + kb + 4], a3 = As[(r + 8) * SA + kb + 4];
            #pragma unroll
            for (int n = 0; n < 4; n++)
                mma8(c[m][n][0], c[m][n][1], c[m][n][2], c[m][n][3], a0, a1, a2, a3, b[n][0], b[n][1]);
        }
    }

    #pragma unroll
    for (int m = 0; m < 8; m++) {
        #pragma unroll
        for (int n = 0; n < 4; n++) {
            int col = n0 + n * 8 + 2 * t4;
            #pragma unroll
            for (int h = 0; h < 2; h++) {         // h=0: rows g, h=1: rows g+8
                int row = row0 + m * 16 + g + h * 8;
                if (row < N_NODES) {
                    float v0 = c[m][n][2 * h], v1 = c[m][n][2 * h + 1];
                    float* dst = Cout + (size_t)row * 128 + col;
                    if (MODE == 1) { v0 = ssp_fast(v0 + bsm[col]); v1 = ssp_fast(v1 + bsm[col + 1]); }
                    if (MODE == 2) {
                        float2 old = *(float2*)dst;
                        v0 += bsm[col] + old.x; v1 += bsm[col + 1] + old.y;
                    }
                    *(float2*)dst = make_float2(v0, v1);
                }
            }
        }
    }
}

// ---------------- fused edge kernel (warp MMA) --------------------------------
#define SA1 68   // stride for [128][64] gaussian tile
__global__ __launch_bounds__(128) void edge_mm(const float* __restrict__ w1,
                                               const float* __restrict__ b1,
                                               const float* __restrict__ w2,
                                               const float* __restrict__ b2) {
    extern __shared__ u32 sm[];
    u32* As1 = sm;                       // [128][SA1] tf32 gaussians
    u32* Bs1 = As1 + 128 * SA1;          // [64][SA]   tf32 w1 (k-major)
    u32* As2 = Bs1 + 64 * SA;            // [128][SA]  tf32 t / f32 D2 staging
    u32* Bs2 = As2 + 128 * SA;           // [128][SA]  tf32 w2
    float* sC  = (float*)(Bs2 + 128 * SA);
    int*   sS  = (int*)(sC + 128);
    int*   sD  = sS + 128;
    float* b1s = (float*)(sD + 128);
    float* b2s = b1s + 128;

    int tid = threadIdx.x, lane = tid & 31, w = tid >> 5;
    int g = lane >> 2, t4 = lane & 3;
    int n0 = w * 32;

    for (int i = tid; i < 64 * 128; i += 128) {     // Bs1[k][n], zero-pad k>=50
        int k = i >> 7, n = i & 127;
        Bs1[k * SA + n] = (k < NG) ? f2tf(w1[k * 128 + n]) : 0u;
    }
    for (int i = tid; i < 16384; i += 128) {        // Bs2[k][n]
        int k = i >> 7, n = i & 127;
        Bs2[k * SA + n] = f2tf(w2[i]);
    }
    b1s[tid] = b1[tid];
    b2s[tid] = b2[tid];
    __syncthreads();

    const float L2E = 1.4426950408889634f;
    const float step = 5.0f / 49.0f;
    const float c2 = (-0.5f / (step * step)) * L2E;

    for (int tile = blockIdx.x; tile < E_EDGES / 128; tile += gridDim.x) {
        int e = tile * 128 + tid;
        float d = g_d[e];
        sC[tid] = g_C[e]; sS[tid] = g_src[e]; sD[tid] = g_dst[e];
        float sr = d * 0.2f;
        float l2env = -1e30f;
        if (sr < 1.f) l2env = (1.f - __frcp_rn(1.f - sr * sr)) * L2E;
        #pragma unroll
        for (int k = 0; k < 64; k++) {
            float t0 = d - step * (float)k;
            As1[tid * SA1 + k] = (k < NG) ? f2tf(ex2f(c2 * t0 * t0 + l2env)) : 0u;
        }
        __syncthreads();

        float c[8][4][4];
        #pragma unroll
        for (int m = 0; m < 8; m++)
            #pragma unroll
            for (int n = 0; n < 4; n++)
                #pragma unroll
                for (int q = 0; q < 4; q++) c[m][n][q] = 0.f;

        // phase 1: [128x64] @ w1[64x128]
        #pragma unroll
        for (int kk = 0; kk < 8; kk++) {
            int kb = kk * 8 + t4;
            u32 b[4][2];
            #pragma unroll
            for (int n = 0; n < 4; n++) {
                int col = n0 + n * 8 + g;
                b[n][0] = Bs1[kb * SA + col];
                b[n][1] = Bs1[(kb + 4) * SA + col];
            }
            #pragma unroll
            for (int m = 0; m < 8; m++) {
                int r = m * 16 + g;
                u32 a0 = As1[r * SA1 + kb], a1 = As1[(r + 8) * SA1 + kb];
                u32 a2 = As1[r * SA1 + kb + 4], a3 = As1[(r + 8) * SA1 + kb + 4];
                #pragma unroll
                for (int n = 0; n < 4; n++)
                    mma8(c[m][n][0], c[m][n][1], c[m][n][2], c[m][n][3], a0, a1, a2, a3, b[n][0], b[n][1]);
            }
        }
        // t = ssp(D1+b1) -> As2 (tf32)
        #pragma unroll
        for (int m = 0; m < 8; m++)
            #pragma unroll
            for (int n = 0; n < 4; n++) {
                int col = n0 + n * 8 + 2 * t4;
                #pragma unroll
                for (int h = 0; h < 2; h++) {
                    int row = m * 16 + g + h * 8;
                    As2[row * SA + col]     = f2tf(ssp_fast(c[m][n][2 * h]     + b1s[col]));
                    As2[row * SA + col + 1] = f2tf(ssp_fast(c[m][n][2 * h + 1] + b1s[col + 1]));
                }
            }
        __syncthreads();

        // phase 2: [128x128] @ w2[128x128]
        #pragma unroll
        for (int m = 0; m < 8; m++)
            #pragma unroll
            for (int n = 0; n < 4; n++)
                #pragma unroll
                for (int q = 0; q < 4; q++) c[m][n][q] = 0.f;
        #pragma unroll
        for (int kk = 0; kk < 16; kk++) {
            int kb = kk * 8 + t4;
            u32 b[4][2];
            #pragma unroll
            for (int n = 0; n < 4; n++) {
                int col = n0 + n * 8 + g;
                b[n][0] = Bs2[kb * SA + col];
                b[n][1] = Bs2[(kb + 4) * SA + col];
            }
            #pragma unroll
            for (int m = 0; m < 8; m++) {
                int r = m * 16 + g;
                u32 a0 = As2[r * SA + kb], a1 = As2[(r + 8) * SA + kb];
                u32 a2 = As2[r * SA + kb + 4], a3 = As2[(r + 8) * SA + kb + 4];
                #pragma unroll
                for (int n = 0; n < 4; n++)
                    mma8(c[m][n][0], c[m][n][1], c[m][n][2], c[m][n][3], a0, a1, a2, a3, b[n][0], b[n][1]);
            }
        }
        __syncthreads();   // all warps done reading As2 before overwrite

        // stage D2 (raw f32) into As2
        float* Df = (float*)As2;
        #pragma unroll
        for (int m = 0; m < 8; m++)
            #pragma unroll
            for (int n = 0; n < 4; n++) {
                int col = n0 + n * 8 + 2 * t4;
                #pragma unroll
                for (int h = 0; h < 2; h++) {
                    int row = m * 16 + g + h * 8;
                    Df[row * SA + col]     = c[m][n][2 * h];
                    Df[row * SA + col + 1] = c[m][n][2 * h + 1];
                }
            }
        __syncthreads();

        // epilogue: per edge, all 128 threads coalesced
        float bb = b2s[tid];
        #pragma unroll 2
        for (int ee = 0; ee < 128; ee++) {
            float v = (Df[ee * SA + tid] + bb) * sC[ee] * g_xf[(size_t)sS[ee] * 128 + tid];
            redf(&g_agg[(size_t)sD[ee] * 128 + tid], v);
        }
        __syncthreads();
    }
}

// ---------------- readout ----------------------------------------------------
__global__ __launch_bounds__(128) void readout_kernel(const float* __restrict__ w1,
                                                      const float* __restrict__ b1,
                                                      const float* __restrict__ w2,
                                                      const float* __restrict__ b2v,
                                                      const int* __restrict__ batch,
                                                      float* __restrict__ out) {
    __shared__ float w1s[128 * 64];
    __shared__ float w2s2[64];
    __shared__ float hs[2][128];
    __shared__ float red[2][64];
    int tid = threadIdx.x;
    for (int i = tid; i < 128 * 64; i += 128) w1s[i] = w1[i];
    if (tid < 64) w2s2[tid] = w2[tid];
    __syncthreads();
    int half = tid >> 6, c = tid & 63;
    float b1r = b1[c], b2r = b2v[0];
    const int npairs = N_NODES / 2;
    for (int pair = blockIdx.x; pair < npairs; pair += gridDim.x) {
        for (int i = tid; i < 256; i += 128)
            hs[i >> 7][i & 127] = g_h[(size_t)(pair * 2 + (i >> 7)) * 128 + (i & 127)];
        __syncthreads();
        float acc = b1r;
        #pragma unroll 4
        for (int k = 0; k < 128; k++) acc += hs[half][k] * w1s[k * 64 + c];
        red[half][c] = sspf(acc) * w2s2[c];
        __syncthreads();
        if (c < 32) {
            float v = red[half][c] + red[half][c + 32];
            #pragma unroll
            for (int off = 16; off >= 1; off >>= 1) v += __shfl_down_sync(0xffffffffu, v, off);
            if (c == 0) atomicAdd(&out[batch[pair * 2 + half]], v + b2r);
        }
        __syncthreads();
    }
}

// ---------------- launch ------------------------------------------------------
extern "C" void kernel_launch(void* const* d_in, const int* in_sizes, int n_in,
                              void* d_out, int out_size) {
    const int*   z       = (const int*)d_in[0];
    const float* pos     = (const float*)d_in[1];
    const int*   ei      = (const int*)d_in[2];
    const int*   batch   = (const int*)d_in[3];
    const float* emb     = (const float*)d_in[4];
    const float* mlp_w1  = (const float*)d_in[5];
    const float* mlp_b1  = (const float*)d_in[6];
    const float* mlp_w2  = (const float*)d_in[7];
    const float* mlp_b2  = (const float*)d_in[8];
    const float* conv1_w = (const float*)d_in[9];
    const float* conv2_w = (const float*)d_in[10];
    const float* conv2_b = (const float*)d_in[11];
    const float* lin_w   = (const float*)d_in[12];
    const float* lin_b   = (const float*)d_in[13];
    const float* out1_w  = (const float*)d_in[14];
    const float* out1_b  = (const float*)d_in[15];
    const float* out2_w  = (const float*)d_in[16];
    const float* out2_b  = (const float*)d_in[17];

    const int GEMM_SMEM = (2 * 128 * SA + 128) * 4;                              // ~135.7 KB
    const int EDGE_SMEM = (128 * SA1 + 64 * SA + 128 * SA * 2 + 128 * 5) * 4;    // ~206.3 KB
    cudaFuncSetAttribute(mm_gemm<0>, cudaFuncAttributeMaxDynamicSharedMemorySize, GEMM_SMEM);
    cudaFuncSetAttribute(mm_gemm<1>, cudaFuncAttributeMaxDynamicSharedMemorySize, GEMM_SMEM);
    cudaFuncSetAttribute(mm_gemm<2>, cudaFuncAttributeMaxDynamicSharedMemorySize, GEMM_SMEM);
    cudaFuncSetAttribute(edge_mm, cudaFuncAttributeMaxDynamicSharedMemorySize, EDGE_SMEM);

    float *hP, *xfP, *aggP;
    cudaGetSymbolAddress((void**)&hP, g_h);
    cudaGetSymbolAddress((void**)&xfP, g_xf);
    cudaGetSymbolAddress((void**)&aggP, g_agg);

    detect_kernel<<<1, 32>>>(ei);
    prep_kernel<<<(E_EDGES + 255) / 256, 256>>>(ei, pos);
    embed_kernel<<<(N_NODES * 128 + 255) / 256, 256>>>(z, emb);

    const int gg = (N_NODES + 127) / 128;   // 391
    for (int l = 0; l < 3; l++) {
        mm_gemm<0><<<gg, 128, GEMM_SMEM>>>(hP, conv1_w + (size_t)l * 16384, nullptr, xfP);
        cudaMemsetAsync(aggP, 0, (size_t)N_NODES * 128 * sizeof(float));
        edge_mm<<<148, 128, EDGE_SMEM>>>(mlp_w1 + (size_t)l * NG * 128,
                                         mlp_b1 + (size_t)l * 128,
                                         mlp_w2 + (size_t)l * 16384,
                                         mlp_b2 + (size_t)l * 128);
        mm_gemm<1><<<gg, 128, GEMM_SMEM>>>(aggP, conv2_w + (size_t)l * 16384,
                                           conv2_b + (size_t)l * 128, xfP);
        mm_gemm<2><<<gg, 128, GEMM_SMEM>>>(xfP, lin_w + (size_t)l * 16384,
                                           lin_b + (size_t)l * 128, hP);
    }

    cudaMemsetAsync(d_out, 0, NGRAPHS * sizeof(float));
    readout_kernel<<<1024, 128>>>(out1_w, out1_b, out2_w, out2_b, batch, (float*)d_out);
}

// round 7
// speedup vs baseline: 2.6879x; 2.0144x over previous
#include <cuda_runtime.h>
#include <math.h>

#define N_NODES 50000
#define E_EDGES 640000
#define NG 50
#define NGRAPHS 64

typedef unsigned int u32;

// ---------------- scratch ----------------------------------------------------
__device__ __align__(16) float g_d[E_EDGES];
__device__ __align__(16) float g_C[E_EDGES];
__device__ __align__(16) int   g_src[E_EDGES];
__device__ __align__(16) int   g_dst[E_EDGES];
__device__ __align__(16) float g_h[(size_t)N_NODES * 128];
__device__ __align__(16) float g_xf[(size_t)N_NODES * 128];
__device__ __align__(16) float g_agg[(size_t)N_NODES * 128];
__device__ int g_is64;

// ---------------- helpers -----------------------------------------------------
__device__ __forceinline__ u32 f2tf(float f) {
    u32 r; asm("cvt.rna.tf32.f32 %0,%1;" : "=r"(r) : "f"(f)); return r;
}
__device__ __forceinline__ void mma8(float& c0, float& c1, float& c2, float& c3,
                                     u32 a0, u32 a1, u32 a2, u32 a3, u32 b0, u32 b1) {
    asm("mma.sync.aligned.m16n8k8.row.col.f32.tf32.tf32.f32 "
        "{%0,%1,%2,%3},{%4,%5,%6,%7},{%8,%9},{%0,%1,%2,%3};"
        : "+f"(c0), "+f"(c1), "+f"(c2), "+f"(c3)
        : "r"(a0), "r"(a1), "r"(a2), "r"(a3), "r"(b0), "r"(b1));
}
__device__ __forceinline__ float ex2f(float x) { float r; asm("ex2.approx.ftz.f32 %0,%1;" : "=f"(r) : "f"(x)); return r; }
__device__ __forceinline__ float lg2f_(float x) { float r; asm("lg2.approx.ftz.f32 %0,%1;" : "=f"(r) : "f"(x)); return r; }
__device__ __forceinline__ float ssp_fast(float x) {
    float e = ex2f(x * 1.4426950408889634f);
    return 0.6931471805599453f * (lg2f_(1.0f + e) - 1.0f);
}
__device__ __forceinline__ float sspf(float x) {
    float ax = fabsf(x);
    float sp = log1pf(__expf(-ax));
    return (x > 0.f ? x + sp : sp) - 0.6931471805599453f;
}
__device__ __forceinline__ void red2(float* p, float v0, float v1) {
    asm volatile("red.global.add.v2.f32 [%0], {%1,%2};" :: "l"(p), "f"(v0), "f"(v1) : "memory");
}

// ---------------- small kernels ----------------------------------------------
__global__ void detect_kernel(const int* __restrict__ ei) {
    if (threadIdx.x == 0 && blockIdx.x == 0) {
        int acc = ei[1] | ei[3] | ei[5] | ei[7] | ei[9] | ei[11] | ei[13] | ei[15];
        g_is64 = (acc == 0) ? 1 : 0;
    }
}
__global__ void prep_kernel(const int* __restrict__ ei, const float* __restrict__ pos) {
    int e = blockIdx.x * blockDim.x + threadIdx.x;
    if (e >= E_EDGES) return;
    int s, t;
    if (g_is64) { const long long* q = (const long long*)ei; s = (int)q[e]; t = (int)q[E_EDGES + e]; }
    else { s = ei[e]; t = ei[E_EDGES + e]; }
    float dx = pos[t * 3 + 0] - pos[s * 3 + 0];
    float dy = pos[t * 3 + 1] - pos[s * 3 + 1];
    float dz = pos[t * 3 + 2] - pos[s * 3 + 2];
    float d = sqrtf(dx * dx + dy * dy + dz * dz);
    g_src[e] = s; g_dst[e] = t; g_d[e] = d;
    g_C[e] = 0.5f * (cosf(d * 0.62831853071795864f) + 1.0f);
}
__global__ void embed_kernel(const int* __restrict__ z, const float* __restrict__ emb) {
    int i = blockIdx.x * blockDim.x + threadIdx.x;
    if (i >= N_NODES * 128) return;
    g_h[i] = emb[z[i >> 7] * 128 + (i & 127)];
}

#define SA 132
#define SA1 68

// ---------------- node GEMM: C = A @ W (conv1) --------------------------------
__global__ __launch_bounds__(256) void mm_conv1(const float* __restrict__ A,
                                                const float* __restrict__ W,
                                                float* __restrict__ Cout) {
    extern __shared__ u32 sm[];
    u32* As = sm;
    u32* Bs = sm + 128 * SA;
    int tid = threadIdx.x, lane = tid & 31, w = tid >> 5;
    int row0 = blockIdx.x * 128;

    for (int i = tid; i < 16384; i += 256) {
        int r = i >> 7, k = i & 127;
        float v = (row0 + r < N_NODES) ? A[(size_t)(row0 + r) * 128 + k] : 0.f;
        As[r * SA + k] = f2tf(v);
        Bs[r * SA + k] = f2tf(W[i]);
    }
    __syncthreads();

    int g = lane >> 2, t4 = lane & 3;
    int n0 = w * 16;
    float c[8][2][4];
    #pragma unroll
    for (int m = 0; m < 8; m++)
        #pragma unroll
        for (int n = 0; n < 2; n++)
            #pragma unroll
            for (int q = 0; q < 4; q++) c[m][n][q] = 0.f;

    #pragma unroll
    for (int kk = 0; kk < 16; kk++) {
        int kb = kk * 8 + t4;
        u32 b[2][2];
        #pragma unroll
        for (int n = 0; n < 2; n++) {
            int col = n0 + n * 8 + g;
            b[n][0] = Bs[kb * SA + col];
            b[n][1] = Bs[(kb + 4) * SA + col];
        }
        #pragma unroll
        for (int m = 0; m < 8; m++) {
            int r = m * 16 + g;
            u32 a0 = As[r * SA + kb], a1 = As[(r + 8) * SA + kb];
            u32 a2 = As[r * SA + kb + 4], a3 = As[(r + 8) * SA + kb + 4];
            #pragma unroll
            for (int n = 0; n < 2; n++)
                mma8(c[m][n][0], c[m][n][1], c[m][n][2], c[m][n][3], a0, a1, a2, a3, b[n][0], b[n][1]);
        }
    }
    #pragma unroll
    for (int m = 0; m < 8; m++)
        #pragma unroll
        for (int n = 0; n < 2; n++) {
            int col = n0 + n * 8 + 2 * t4;
            #pragma unroll
            for (int h = 0; h < 2; h++) {
                int row = row0 + m * 16 + g + h * 8;
                if (row < N_NODES)
                    *(float2*)(Cout + (size_t)row * 128 + col) =
                        make_float2(c[m][n][2 * h], c[m][n][2 * h + 1]);
            }
        }
}

// ---------------- fused conv2+lin: h += ssp(agg@W2+b2)@W3 + b3 ----------------
__global__ __launch_bounds__(256) void mm_gemm2(const float* __restrict__ Agg,
                                                const float* __restrict__ W2,
                                                const float* __restrict__ b2,
                                                const float* __restrict__ W3,
                                                const float* __restrict__ b3,
                                                float* __restrict__ H) {
    extern __shared__ u32 sm[];
    u32* As  = sm;
    u32* W2s = sm + 128 * SA;
    u32* W3s = W2s + 128 * SA;
    float* b2s = (float*)(W3s + 128 * SA);
    float* b3s = b2s + 128;
    int tid = threadIdx.x, lane = tid & 31, w = tid >> 5;
    int row0 = blockIdx.x * 128;

    for (int i = tid; i < 16384; i += 256) {
        int r = i >> 7, k = i & 127;
        float v = (row0 + r < N_NODES) ? Agg[(size_t)(row0 + r) * 128 + k] : 0.f;
        As[r * SA + k] = f2tf(v);
        W2s[r * SA + k] = f2tf(W2[i]);
        W3s[r * SA + k] = f2tf(W3[i]);
    }
    if (tid < 128) { b2s[tid] = b2[tid]; b3s[tid] = b3[tid]; }
    __syncthreads();

    int g = lane >> 2, t4 = lane & 3;
    int n0 = w * 16;
    float c[8][2][4];
    #pragma unroll
    for (int m = 0; m < 8; m++)
        #pragma unroll
        for (int n = 0; n < 2; n++)
            #pragma unroll
            for (int q = 0; q < 4; q++) c[m][n][q] = 0.f;

    #pragma unroll
    for (int kk = 0; kk < 16; kk++) {
        int kb = kk * 8 + t4;
        u32 b[2][2];
        #pragma unroll
        for (int n = 0; n < 2; n++) {
            int col = n0 + n * 8 + g;
            b[n][0] = W2s[kb * SA + col];
            b[n][1] = W2s[(kb + 4) * SA + col];
        }
        #pragma unroll
        for (int m = 0; m < 8; m++) {
            int r = m * 16 + g;
            u32 a0 = As[r * SA + kb], a1 = As[(r + 8) * SA + kb];
            u32 a2 = As[r * SA + kb + 4], a3 = As[(r + 8) * SA + kb + 4];
            #pragma unroll
            for (int n = 0; n < 2; n++)
                mma8(c[m][n][0], c[m][n][1], c[m][n][2], c[m][n][3], a0, a1, a2, a3, b[n][0], b[n][1]);
        }
    }
    __syncthreads();   // all phase-1 reads of As done

    // t = ssp(c + b2) -> As (in place)
    #pragma unroll
    for (int m = 0; m < 8; m++)
        #pragma unroll
        for (int n = 0; n < 2; n++) {
            int col = n0 + n * 8 + 2 * t4;
            #pragma unroll
            for (int h = 0; h < 2; h++) {
                int row = m * 16 + g + h * 8;
                As[row * SA + col]     = f2tf(ssp_fast(c[m][n][2 * h]     + b2s[col]));
                As[row * SA + col + 1] = f2tf(ssp_fast(c[m][n][2 * h + 1] + b2s[col + 1]));
            }
        }
    __syncthreads();

    #pragma unroll
    for (int m = 0; m < 8; m++)
        #pragma unroll
        for (int n = 0; n < 2; n++)
            #pragma unroll
            for (int q = 0; q < 4; q++) c[m][n][q] = 0.f;
    #pragma unroll
    for (int kk = 0; kk < 16; kk++) {
        int kb = kk * 8 + t4;
        u32 b[2][2];
        #pragma unroll
        for (int n = 0; n < 2; n++) {
            int col = n0 + n * 8 + g;
            b[n][0] = W3s[kb * SA + col];
            b[n][1] = W3s[(kb + 4) * SA + col];
        }
        #pragma unroll
        for (int m = 0; m < 8; m++) {
            int r = m * 16 + g;
            u32 a0 = As[r * SA + kb], a1 = As[(r + 8) * SA + kb];
            u32 a2 = As[r * SA + kb + 4], a3 = As[(r + 8) * SA + kb + 4];
            #pragma unroll
            for (int n = 0; n < 2; n++)
                mma8(c[m][n][0], c[m][n][1], c[m][n][2], c[m][n][3], a0, a1, a2, a3, b[n][0], b[n][1]);
        }
    }
    #pragma unroll
    for (int m = 0; m < 8; m++)
        #pragma unroll
        for (int n = 0; n < 2; n++) {
            int col = n0 + n * 8 + 2 * t4;
            #pragma unroll
            for (int h = 0; h < 2; h++) {
                int row = row0 + m * 16 + g + h * 8;
                if (row < N_NODES) {
                    float* dst = H + (size_t)row * 128 + col;
                    float2 old = *(float2*)dst;
                    *(float2*)dst = make_float2(old.x + c[m][n][2 * h] + b3s[col],
                                                old.y + c[m][n][2 * h + 1] + b3s[col + 1]);
                }
            }
        }
}

// ---------------- fused edge kernel (warp MMA, register epilogue) -------------
__global__ __launch_bounds__(256) void edge_mm(const float* __restrict__ w1,
                                               const float* __restrict__ b1,
                                               const float* __restrict__ w2,
                                               const float* __restrict__ b2) {
    extern __shared__ u32 sm[];
    u32* As1 = sm;                       // [128][SA1] tf32 gaussians
    u32* Bs1 = As1 + 128 * SA1;          // [64][SA]   tf32 w1
    u32* As2 = Bs1 + 64 * SA;            // [128][SA]  tf32 t
    u32* Bs2 = As2 + 128 * SA;           // [128][SA]  tf32 w2
    float* sC  = (float*)(Bs2 + 128 * SA);
    int*   sS  = (int*)(sC + 128);
    int*   sD  = sS + 128;
    float* b1s = (float*)(sD + 128);
    float* b2s = b1s + 128;

    int tid = threadIdx.x, lane = tid & 31, w = tid >> 5;
    int g = lane >> 2, t4 = lane & 3;
    int n0 = w * 16;

    for (int i = tid; i < 64 * 128; i += 256) {
        int k = i >> 7, n = i & 127;
        Bs1[k * SA + n] = (k < NG) ? f2tf(w1[k * 128 + n]) : 0u;
    }
    for (int i = tid; i < 16384; i += 256) {
        int k = i >> 7, n = i & 127;
        Bs2[k * SA + n] = f2tf(w2[i]);
    }
    if (tid < 128) { b1s[tid] = b1[tid]; b2s[tid] = b2[tid]; }
    __syncthreads();

    const float L2E = 1.4426950408889634f;
    const float step = 5.0f / 49.0f;
    const float c2 = (-0.5f / (step * step)) * L2E;

    for (int tile = blockIdx.x; tile < E_EDGES / 128; tile += gridDim.x) {
        // metadata (threads 0-127)
        if (tid < 128) {
            int e = tile * 128 + tid;
            sC[tid] = g_C[e]; sS[tid] = g_src[e]; sD[tid] = g_dst[e];
        }
        // gaussians: 2 threads per edge, 32 cols each
        {
            int el = tid >> 1, half = tid & 1;
            float d = g_d[tile * 128 + el];
            float sr = d * 0.2f;
            float l2env = -1e30f;
            if (sr < 1.f) l2env = (1.f - __frcp_rn(1.f - sr * sr)) * L2E;
            #pragma unroll
            for (int j = 0; j < 32; j++) {
                int k = half * 32 + j;
                float t0 = d - step * (float)k;
                As1[el * SA1 + k] = (k < NG) ? f2tf(ex2f(c2 * t0 * t0 + l2env)) : 0u;
            }
        }
        __syncthreads();

        float c[8][2][4];
        #pragma unroll
        for (int m = 0; m < 8; m++)
            #pragma unroll
            for (int n = 0; n < 2; n++)
                #pragma unroll
                for (int q = 0; q < 4; q++) c[m][n][q] = 0.f;

        // phase 1: [128x64] @ w1
        #pragma unroll
        for (int kk = 0; kk < 8; kk++) {
            int kb = kk * 8 + t4;
            u32 b[2][2];
            #pragma unroll
            for (int n = 0; n < 2; n++) {
                int col = n0 + n * 8 + g;
                b[n][0] = Bs1[kb * SA + col];
                b[n][1] = Bs1[(kb + 4) * SA + col];
            }
            #pragma unroll
            for (int m = 0; m < 8; m++) {
                int r = m * 16 + g;
                u32 a0 = As1[r * SA1 + kb], a1 = As1[(r + 8) * SA1 + kb];
                u32 a2 = As1[r * SA1 + kb + 4], a3 = As1[(r + 8) * SA1 + kb + 4];
                #pragma unroll
                for (int n = 0; n < 2; n++)
                    mma8(c[m][n][0], c[m][n][1], c[m][n][2], c[m][n][3], a0, a1, a2, a3, b[n][0], b[n][1]);
            }
        }
        // t = ssp(D1+b1) -> As2
        #pragma unroll
        for (int m = 0; m < 8; m++)
            #pragma unroll
            for (int n = 0; n < 2; n++) {
                int col = n0 + n * 8 + 2 * t4;
                #pragma unroll
                for (int h = 0; h < 2; h++) {
                    int row = m * 16 + g + h * 8;
                    As2[row * SA + col]     = f2tf(ssp_fast(c[m][n][2 * h]     + b1s[col]));
                    As2[row * SA + col + 1] = f2tf(ssp_fast(c[m][n][2 * h + 1] + b1s[col + 1]));
                }
            }
        __syncthreads();

        // phase 2: [128x128] @ w2
        #pragma unroll
        for (int m = 0; m < 8; m++)
            #pragma unroll
            for (int n = 0; n < 2; n++)
                #pragma unroll
                for (int q = 0; q < 4; q++) c[m][n][q] = 0.f;
        #pragma unroll
        for (int kk = 0; kk < 16; kk++) {
            int kb = kk * 8 + t4;
            u32 b[2][2];
            #pragma unroll
            for (int n = 0; n < 2; n++) {
                int col = n0 + n * 8 + g;
                b[n][0] = Bs2[kb * SA + col];
                b[n][1] = Bs2[(kb + 4) * SA + col];
            }
            #pragma unroll
            for (int m = 0; m < 8; m++) {
                int r = m * 16 + g;
                u32 a0 = As2[r * SA + kb], a1 = As2[(r + 8) * SA + kb];
                u32 a2 = As2[r * SA + kb + 4], a3 = As2[(r + 8) * SA + kb + 4];
                #pragma unroll
                for (int n = 0; n < 2; n++)
                    mma8(c[m][n][0], c[m][n][1], c[m][n][2], c[m][n][3], a0, a1, a2, a3, b[n][0], b[n][1]);
            }
        }

        // register epilogue: msg = (D2+b2)*C*xf[src] -> red to agg[dst]
        #pragma unroll
        for (int m = 0; m < 8; m++) {
            #pragma unroll
            for (int h = 0; h < 2; h++) {
                int el = m * 16 + g + h * 8;
                float Cv = sC[el];
                const float* xfp = g_xf + (size_t)sS[el] * 128;
                float* agp = g_agg + (size_t)sD[el] * 128;
                #pragma unroll
                for (int n = 0; n < 2; n++) {
                    int col = n0 + n * 8 + 2 * t4;
                    float2 x = *(const float2*)(xfp + col);
                    float v0 = (c[m][n][2 * h]     + b2s[col])     * Cv * x.x;
                    float v1 = (c[m][n][2 * h + 1] + b2s[col + 1]) * Cv * x.y;
                    red2(agp + col, v0, v1);
                }
            }
        }
        __syncthreads();   // protect As1/metadata for next tile
    }
}

// ---------------- readout ----------------------------------------------------
__global__ __launch_bounds__(128) void readout_kernel(const float* __restrict__ w1,
                                                      const float* __restrict__ b1,
                                                      const float* __restrict__ w2,
                                                      const float* __restrict__ b2v,
                                                      const int* __restrict__ batch,
                                                      float* __restrict__ out) {
    __shared__ float w1s[128 * 64];
    __shared__ float w2s2[64];
    __shared__ float hs[2][128];
    __shared__ float red[2][64];
    int tid = threadIdx.x;
    for (int i = tid; i < 128 * 64; i += 128) w1s[i] = w1[i];
    if (tid < 64) w2s2[tid] = w2[tid];
    __syncthreads();
    int half = tid >> 6, c = tid & 63;
    float b1r = b1[c], b2r = b2v[0];
    const int npairs = N_NODES / 2;
    for (int pair = blockIdx.x; pair < npairs; pair += gridDim.x) {
        for (int i = tid; i < 256; i += 128)
            hs[i >> 7][i & 127] = g_h[(size_t)(pair * 2 + (i >> 7)) * 128 + (i & 127)];
        __syncthreads();
        float acc = b1r;
        #pragma unroll 4
        for (int k = 0; k < 128; k++) acc += hs[half][k] * w1s[k * 64 + c];
        red[half][c] = sspf(acc) * w2s2[c];
        __syncthreads();
        if (c < 32) {
            float v = red[half][c] + red[half][c + 32];
            #pragma unroll
            for (int off = 16; off >= 1; off >>= 1) v += __shfl_down_sync(0xffffffffu, v, off);
            if (c == 0) atomicAdd(&out[batch[pair * 2 + half]], v + b2r);
        }
        __syncthreads();
    }
}

// ---------------- launch ------------------------------------------------------
extern "C" void kernel_launch(void* const* d_in, const int* in_sizes, int n_in,
                              void* d_out, int out_size) {
    const int*   z       = (const int*)d_in[0];
    const float* pos     = (const float*)d_in[1];
    const int*   ei      = (const int*)d_in[2];
    const int*   batch   = (const int*)d_in[3];
    const float* emb     = (const float*)d_in[4];
    const float* mlp_w1  = (const float*)d_in[5];
    const float* mlp_b1  = (const float*)d_in[6];
    const float* mlp_w2  = (const float*)d_in[7];
    const float* mlp_b2  = (const float*)d_in[8];
    const float* conv1_w = (const float*)d_in[9];
    const float* conv2_w = (const float*)d_in[10];
    const float* conv2_b = (const float*)d_in[11];
    const float* lin_w   = (const float*)d_in[12];
    const float* lin_b   = (const float*)d_in[13];
    const float* out1_w  = (const float*)d_in[14];
    const float* out1_b  = (const float*)d_in[15];
    const float* out2_w  = (const float*)d_in[16];
    const float* out2_b  = (const float*)d_in[17];

    const int CONV1_SMEM = 2 * 128 * SA * 4;                                  // 135168
    const int GEMM2_SMEM = 3 * 128 * SA * 4 + 256 * 4;                        // 203776
    const int EDGE_SMEM  = (128 * SA1 + 64 * SA + 2 * 128 * SA + 5 * 128) * 4;// 206336
    cudaFuncSetAttribute(mm_conv1, cudaFuncAttributeMaxDynamicSharedMemorySize, CONV1_SMEM);
    cudaFuncSetAttribute(mm_gemm2, cudaFuncAttributeMaxDynamicSharedMemorySize, GEMM2_SMEM);
    cudaFuncSetAttribute(edge_mm, cudaFuncAttributeMaxDynamicSharedMemorySize, EDGE_SMEM);

    float *hP, *xfP, *aggP;
    cudaGetSymbolAddress((void**)&hP, g_h);
    cudaGetSymbolAddress((void**)&xfP, g_xf);
    cudaGetSymbolAddress((void**)&aggP, g_agg);

    detect_kernel<<<1, 32>>>(ei);
    prep_kernel<<<(E_EDGES + 255) / 256, 256>>>(ei, pos);
    embed_kernel<<<(N_NODES * 128 + 255) / 256, 256>>>(z, emb);

    const int gg = (N_NODES + 127) / 128;   // 391
    for (int l = 0; l < 3; l++) {
        mm_conv1<<<gg, 256, CONV1_SMEM>>>(hP, conv1_w + (size_t)l * 16384, xfP);
        cudaMemsetAsync(aggP, 0, (size_t)N_NODES * 128 * sizeof(float));
        edge_mm<<<148, 256, EDGE_SMEM>>>(mlp_w1 + (size_t)l * NG * 128,
                                         mlp_b1 + (size_t)l * 128,
                                         mlp_w2 + (size_t)l * 16384,
                                         mlp_b2 + (size_t)l * 128);
        mm_gemm2<<<gg, 256, GEMM2_SMEM>>>(aggP, conv2_w + (size_t)l * 16384,
                                          conv2_b + (size_t)l * 128,
                                          lin_w + (size_t)l * 16384,
                                          lin_b + (size_t)l * 128, hP);
    }

    cudaMemsetAsync(d_out, 0, NGRAPHS * sizeof(float));
    readout_kernel<<<1024, 128>>>(out1_w, out1_b, out2_w, out2_b, batch, (float*)d_out);
}

// round 8
// speedup vs baseline: 4.1950x; 1.5607x over previous
#include <cuda_runtime.h>
#include <math.h>

#define N_NODES 50000
#define E_EDGES 640000
#define NG 50
#define NGRAPHS 64

typedef unsigned int u32;

// ---------------- scratch ----------------------------------------------------
__device__ __align__(16) float g_d[E_EDGES];
__device__ __align__(16) float g_C[E_EDGES];
__device__ __align__(16) int   g_src[E_EDGES];
__device__ __align__(16) int   g_dst[E_EDGES];
__device__ __align__(16) float g_h[(size_t)N_NODES * 128];
__device__ __align__(16) float g_xf[(size_t)N_NODES * 128];
__device__ __align__(16) float g_agg[(size_t)N_NODES * 128];
__device__ int g_is64;

// ---------------- helpers -----------------------------------------------------
__device__ __forceinline__ u32 f2tf(float f) {
    u32 r; asm("cvt.rna.tf32.f32 %0,%1;" : "=r"(r) : "f"(f)); return r;
}
__device__ __forceinline__ u32 pack_bf(float lo, float hi) {
    u32 r; asm("cvt.rn.bf16x2.f32 %0,%1,%2;" : "=r"(r) : "f"(hi), "f"(lo)); return r;
}
__device__ __forceinline__ void mma8(float& c0, float& c1, float& c2, float& c3,
                                     u32 a0, u32 a1, u32 a2, u32 a3, u32 b0, u32 b1) {
    asm("mma.sync.aligned.m16n8k8.row.col.f32.tf32.tf32.f32 "
        "{%0,%1,%2,%3},{%4,%5,%6,%7},{%8,%9},{%0,%1,%2,%3};"
        : "+f"(c0), "+f"(c1), "+f"(c2), "+f"(c3)
        : "r"(a0), "r"(a1), "r"(a2), "r"(a3), "r"(b0), "r"(b1));
}
__device__ __forceinline__ void mma16(float& c0, float& c1, float& c2, float& c3,
                                      u32 a0, u32 a1, u32 a2, u32 a3, u32 b0, u32 b1) {
    asm("mma.sync.aligned.m16n8k16.row.col.f32.bf16.bf16.f32 "
        "{%0,%1,%2,%3},{%4,%5,%6,%7},{%8,%9},{%0,%1,%2,%3};"
        : "+f"(c0), "+f"(c1), "+f"(c2), "+f"(c3)
        : "r"(a0), "r"(a1), "r"(a2), "r"(a3), "r"(b0), "r"(b1));
}
__device__ __forceinline__ float ex2f(float x) { float r; asm("ex2.approx.ftz.f32 %0,%1;" : "=f"(r) : "f"(x)); return r; }
__device__ __forceinline__ float lg2f_(float x) { float r; asm("lg2.approx.ftz.f32 %0,%1;" : "=f"(r) : "f"(x)); return r; }
__device__ __forceinline__ float ssp_fast(float x) {
    float e = ex2f(x * 1.4426950408889634f);
    return 0.6931471805599453f * (lg2f_(1.0f + e) - 1.0f);
}
__device__ __forceinline__ float sspf(float x) {
    float ax = fabsf(x);
    float sp = log1pf(__expf(-ax));
    return (x > 0.f ? x + sp : sp) - 0.6931471805599453f;
}
__device__ __forceinline__ void red2(float* p, float v0, float v1) {
    asm volatile("red.global.add.v2.f32 [%0], {%1,%2};" :: "l"(p), "f"(v0), "f"(v1) : "memory");
}

// ---------------- small kernels ----------------------------------------------
__global__ void detect_kernel(const int* __restrict__ ei) {
    if (threadIdx.x == 0 && blockIdx.x == 0) {
        int acc = ei[1] | ei[3] | ei[5] | ei[7] | ei[9] | ei[11] | ei[13] | ei[15];
        g_is64 = (acc == 0) ? 1 : 0;
    }
}
__global__ void prep_kernel(const int* __restrict__ ei, const float* __restrict__ pos) {
    int e = blockIdx.x * blockDim.x + threadIdx.x;
    if (e >= E_EDGES) return;
    int s, t;
    if (g_is64) { const long long* q = (const long long*)ei; s = (int)q[e]; t = (int)q[E_EDGES + e]; }
    else { s = ei[e]; t = ei[E_EDGES + e]; }
    float dx = pos[t * 3 + 0] - pos[s * 3 + 0];
    float dy = pos[t * 3 + 1] - pos[s * 3 + 1];
    float dz = pos[t * 3 + 2] - pos[s * 3 + 2];
    float d = sqrtf(dx * dx + dy * dy + dz * dz);
    g_src[e] = s; g_dst[e] = t; g_d[e] = d;
    g_C[e] = 0.5f * (cosf(d * 0.62831853071795864f) + 1.0f);
}
__global__ void embed_kernel(const int* __restrict__ z, const float* __restrict__ emb) {
    int i = blockIdx.x * blockDim.x + threadIdx.x;
    if (i >= N_NODES * 128) return;
    g_h[i] = emb[z[i >> 7] * 128 + (i & 127)];
}

#define SA 132     // tf32 tile stride (floats)
#define W1S 36     // bf16 word stride, K<=64 tiles
#define W2S 68     // bf16 word stride, K=128 tiles

// ---------------- conv1: xf = h @ W  (tf32, 64-row tiles, 2 CTA/SM) ----------
__global__ __launch_bounds__(256, 2) void mm_conv1(const float* __restrict__ A,
                                                   const float* __restrict__ W,
                                                   float* __restrict__ Cout) {
    extern __shared__ u32 sm[];
    u32* As = sm;                 // [64][SA]
    u32* Bs = sm + 64 * SA;       // [128][SA]
    int tid = threadIdx.x, lane = tid & 31, w = tid >> 5;
    int row0 = blockIdx.x * 64;

    for (int i = tid; i < 8192; i += 256) {
        int r = i >> 7, k = i & 127;
        float v = (row0 + r < N_NODES) ? A[(size_t)(row0 + r) * 128 + k] : 0.f;
        As[r * SA + k] = f2tf(v);
    }
    for (int i = tid; i < 16384; i += 256) Bs[(i >> 7) * SA + (i & 127)] = f2tf(W[i]);
    __syncthreads();

    int g = lane >> 2, t4 = lane & 3;
    int n0 = w * 16;
    float c[4][2][4];
    #pragma unroll
    for (int m = 0; m < 4; m++)
        #pragma unroll
        for (int n = 0; n < 2; n++)
            #pragma unroll
            for (int q = 0; q < 4; q++) c[m][n][q] = 0.f;

    #pragma unroll
    for (int kk = 0; kk < 16; kk++) {
        int kb = kk * 8 + t4;
        u32 b[2][2];
        #pragma unroll
        for (int n = 0; n < 2; n++) {
            int col = n0 + n * 8 + g;
            b[n][0] = Bs[kb * SA + col];
            b[n][1] = Bs[(kb + 4) * SA + col];
        }
        #pragma unroll
        for (int m = 0; m < 4; m++) {
            int r = m * 16 + g;
            u32 a0 = As[r * SA + kb], a1 = As[(r + 8) * SA + kb];
            u32 a2 = As[r * SA + kb + 4], a3 = As[(r + 8) * SA + kb + 4];
            #pragma unroll
            for (int n = 0; n < 2; n++)
                mma8(c[m][n][0], c[m][n][1], c[m][n][2], c[m][n][3], a0, a1, a2, a3, b[n][0], b[n][1]);
        }
    }
    #pragma unroll
    for (int m = 0; m < 4; m++)
        #pragma unroll
        for (int n = 0; n < 2; n++) {
            int col = n0 + n * 8 + 2 * t4;
            #pragma unroll
            for (int h = 0; h < 2; h++) {
                int row = row0 + m * 16 + g + h * 8;
                if (row < N_NODES)
                    *(float2*)(Cout + (size_t)row * 128 + col) =
                        make_float2(c[m][n][2 * h], c[m][n][2 * h + 1]);
            }
        }
}

// ---------------- fused conv2+lin (tf32, 64-row tiles, deferred W3) -----------
__global__ __launch_bounds__(256, 2) void mm_gemm2(const float* __restrict__ Agg,
                                                   const float* __restrict__ W2,
                                                   const float* __restrict__ b2,
                                                   const float* __restrict__ W3,
                                                   const float* __restrict__ b3,
                                                   float* __restrict__ H) {
    extern __shared__ u32 sm[];
    u32* As = sm;                 // [64][SA]
    u32* Ws = sm + 64 * SA;       // [128][SA]  (W2, then W3)
    float* b2s = (float*)(Ws + 128 * SA);
    float* b3s = b2s + 128;
    int tid = threadIdx.x, lane = tid & 31, w = tid >> 5;
    int row0 = blockIdx.x * 64;

    for (int i = tid; i < 8192; i += 256) {
        int r = i >> 7, k = i & 127;
        float v = (row0 + r < N_NODES) ? Agg[(size_t)(row0 + r) * 128 + k] : 0.f;
        As[r * SA + k] = f2tf(v);
    }
    for (int i = tid; i < 16384; i += 256) Ws[(i >> 7) * SA + (i & 127)] = f2tf(W2[i]);
    if (tid < 128) { b2s[tid] = b2[tid]; b3s[tid] = b3[tid]; }
    __syncthreads();

    int g = lane >> 2, t4 = lane & 3;
    int n0 = w * 16;
    float c[4][2][4];
    #pragma unroll
    for (int m = 0; m < 4; m++)
        #pragma unroll
        for (int n = 0; n < 2; n++)
            #pragma unroll
            for (int q = 0; q < 4; q++) c[m][n][q] = 0.f;

    #pragma unroll
    for (int kk = 0; kk < 16; kk++) {
        int kb = kk * 8 + t4;
        u32 b[2][2];
        #pragma unroll
        for (int n = 0; n < 2; n++) {
            int col = n0 + n * 8 + g;
            b[n][0] = Ws[kb * SA + col];
            b[n][1] = Ws[(kb + 4) * SA + col];
        }
        #pragma unroll
        for (int m = 0; m < 4; m++) {
            int r = m * 16 + g;
            u32 a0 = As[r * SA + kb], a1 = As[(r + 8) * SA + kb];
            u32 a2 = As[r * SA + kb + 4], a3 = As[(r + 8) * SA + kb + 4];
            #pragma unroll
            for (int n = 0; n < 2; n++)
                mma8(c[m][n][0], c[m][n][1], c[m][n][2], c[m][n][3], a0, a1, a2, a3, b[n][0], b[n][1]);
        }
    }
    __syncthreads();   // phase-1 reads of As and Ws done

    // t = ssp(c + b2) -> As (in place);  Ws <- W3
    #pragma unroll
    for (int m = 0; m < 4; m++)
        #pragma unroll
        for (int n = 0; n < 2; n++) {
            int col = n0 + n * 8 + 2 * t4;
            #pragma unroll
            for (int h = 0; h < 2; h++) {
                int row = m * 16 + g + h * 8;
                As[row * SA + col]     = f2tf(ssp_fast(c[m][n][2 * h]     + b2s[col]));
                As[row * SA + col + 1] = f2tf(ssp_fast(c[m][n][2 * h + 1] + b2s[col + 1]));
            }
        }
    for (int i = tid; i < 16384; i += 256) Ws[(i >> 7) * SA + (i & 127)] = f2tf(W3[i]);
    __syncthreads();

    #pragma unroll
    for (int m = 0; m < 4; m++)
        #pragma unroll
        for (int n = 0; n < 2; n++)
            #pragma unroll
            for (int q = 0; q < 4; q++) c[m][n][q] = 0.f;
    #pragma unroll
    for (int kk = 0; kk < 16; kk++) {
        int kb = kk * 8 + t4;
        u32 b[2][2];
        #pragma unroll
        for (int n = 0; n < 2; n++) {
            int col = n0 + n * 8 + g;
            b[n][0] = Ws[kb * SA + col];
            b[n][1] = Ws[(kb + 4) * SA + col];
        }
        #pragma unroll
        for (int m = 0; m < 4; m++) {
            int r = m * 16 + g;
            u32 a0 = As[r * SA + kb], a1 = As[(r + 8) * SA + kb];
            u32 a2 = As[r * SA + kb + 4], a3 = As[(r + 8) * SA + kb + 4];
            #pragma unroll
            for (int n = 0; n < 2; n++)
                mma8(c[m][n][0], c[m][n][1], c[m][n][2], c[m][n][3], a0, a1, a2, a3, b[n][0], b[n][1]);
        }
    }
    #pragma unroll
    for (int m = 0; m < 4; m++)
        #pragma unroll
        for (int n = 0; n < 2; n++) {
            int col = n0 + n * 8 + 2 * t4;
            #pragma unroll
            for (int h = 0; h < 2; h++) {
                int row = row0 + m * 16 + g + h * 8;
                if (row < N_NODES) {
                    float* dst = H + (size_t)row * 128 + col;
                    float2 old = *(float2*)dst;
                    *(float2*)dst = make_float2(old.x + c[m][n][2 * h] + b3s[col],
                                                old.y + c[m][n][2 * h + 1] + b3s[col + 1]);
                }
            }
        }
}

// ---------------- fused edge kernel (bf16 MMA, 2 CTA/SM) ----------------------
__global__ __launch_bounds__(256, 2) void edge_mm(const float* __restrict__ w1,
                                                  const float* __restrict__ b1,
                                                  const float* __restrict__ w2,
                                                  const float* __restrict__ b2) {
    extern __shared__ u32 sm[];
    u32* As1 = sm;                      // [128 edges][W1S] bf16x2 words (K=64)
    u32* Bs1 = As1 + 128 * W1S;         // [128 n][W1S]
    u32* As2 = Bs1 + 128 * W1S;         // [128 edges][W2S] (K=128)
    u32* Bs2 = As2 + 128 * W2S;         // [128 n][W2S]
    float* sC  = (float*)(Bs2 + 128 * W2S);
    int*   sS  = (int*)(sC + 128);
    int*   sD  = sS + 128;
    float* b1s = (float*)(sD + 128);
    float* b2s = b1s + 128;

    int tid = threadIdx.x, lane = tid & 31, w = tid >> 5;
    int g = lane >> 2, t4 = lane & 3;
    int n0 = w * 16;

    for (int i = tid; i < 128 * 32; i += 256) {     // Bs1[n][word]
        int n = i >> 5, wd = i & 31;
        int k0 = 2 * wd;
        float v0 = (k0 < NG) ? w1[k0 * 128 + n] : 0.f;
        float v1 = (k0 + 1 < NG) ? w1[(k0 + 1) * 128 + n] : 0.f;
        Bs1[n * W1S + wd] = pack_bf(v0, v1);
    }
    for (int i = tid; i < 128 * 64; i += 256) {     // Bs2[n][word]
        int n = i >> 6, wd = i & 63;
        Bs2[n * W2S + wd] = pack_bf(w2[(2 * wd) * 128 + n], w2[(2 * wd + 1) * 128 + n]);
    }
    if (tid < 128) { b1s[tid] = b1[tid]; b2s[tid] = b2[tid]; }
    __syncthreads();

    const float L2E = 1.4426950408889634f;
    const float step = 5.0f / 49.0f;
    const float c2 = (-0.5f / (step * step)) * L2E;

    for (int tile = blockIdx.x; tile < E_EDGES / 128; tile += gridDim.x) {
        if (tid < 128) {
            int e = tile * 128 + tid;
            sC[tid] = g_C[e]; sS[tid] = g_src[e]; sD[tid] = g_dst[e];
        }
        {   // gaussians: 2 threads per edge, 16 bf16x2 words each
            int el = tid >> 1, half = tid & 1;
            float d = g_d[tile * 128 + el];
            float sr = d * 0.2f;
            float l2env = -1e30f;
            if (sr < 1.f) l2env = (1.f - __frcp_rn(1.f - sr * sr)) * L2E;
            #pragma unroll
            for (int j = 0; j < 16; j++) {
                int k = 2 * (half * 16 + j);
                float t0 = d - step * (float)k;
                float t1 = d - step * (float)(k + 1);
                float v0 = (k < NG) ? ex2f(c2 * t0 * t0 + l2env) : 0.f;
                float v1 = (k + 1 < NG) ? ex2f(c2 * t1 * t1 + l2env) : 0.f;
                As1[el * W1S + half * 16 + j] = pack_bf(v0, v1);
            }
        }
        __syncthreads();

        float c[8][2][4];
        #pragma unroll
        for (int m = 0; m < 8; m++)
            #pragma unroll
            for (int n = 0; n < 2; n++)
                #pragma unroll
                for (int q = 0; q < 4; q++) c[m][n][q] = 0.f;

        // phase 1: [128x64] @ w1 (bf16, K=64 -> 4 steps)
        #pragma unroll
        for (int kk = 0; kk < 4; kk++) {
            int wb = kk * 8 + t4;
            u32 b[2][2];
            #pragma unroll
            for (int n = 0; n < 2; n++) {
                int col = n0 + n * 8 + g;
                b[n][0] = Bs1[col * W1S + wb];
                b[n][1] = Bs1[col * W1S + wb + 4];
            }
            #pragma unroll
            for (int m = 0; m < 8; m++) {
                int r = m * 16 + g;
                u32 a0 = As1[r * W1S + wb],     a1 = As1[(r + 8) * W1S + wb];
                u32 a2 = As1[r * W1S + wb + 4], a3 = As1[(r + 8) * W1S + wb + 4];
                #pragma unroll
                for (int n = 0; n < 2; n++)
                    mma16(c[m][n][0], c[m][n][1], c[m][n][2], c[m][n][3], a0, a1, a2, a3, b[n][0], b[n][1]);
            }
        }
        // t = ssp(D1+b1) -> As2 (bf16x2 words; cols 2t4,2t4+1 = one word)
        #pragma unroll
        for (int m = 0; m < 8; m++)
            #pragma unroll
            for (int n = 0; n < 2; n++) {
                int col = n0 + n * 8 + 2 * t4;
                int wd = w * 8 + n * 4 + t4;
                #pragma unroll
                for (int h = 0; h < 2; h++) {
                    int row = m * 16 + g + h * 8;
                    As2[row * W2S + wd] = pack_bf(ssp_fast(c[m][n][2 * h] + b1s[col]),
                                                  ssp_fast(c[m][n][2 * h + 1] + b1s[col + 1]));
                }
            }
        __syncthreads();

        // phase 2: [128x128] @ w2 (bf16, K=128 -> 8 steps)
        #pragma unroll
        for (int m = 0; m < 8; m++)
            #pragma unroll
            for (int n = 0; n < 2; n++)
                #pragma unroll
                for (int q = 0; q < 4; q++) c[m][n][q] = 0.f;
        #pragma unroll
        for (int kk = 0; kk < 8; kk++) {
            int wb = kk * 8 + t4;
            u32 b[2][2];
            #pragma unroll
            for (int n = 0; n < 2; n++) {
                int col = n0 + n * 8 + g;
                b[n][0] = Bs2[col * W2S + wb];
                b[n][1] = Bs2[col * W2S + wb + 4];
            }
            #pragma unroll
            for (int m = 0; m < 8; m++) {
                int r = m * 16 + g;
                u32 a0 = As2[r * W2S + wb],     a1 = As2[(r + 8) * W2S + wb];
                u32 a2 = As2[r * W2S + wb + 4], a3 = As2[(r + 8) * W2S + wb + 4];
                #pragma unroll
                for (int n = 0; n < 2; n++)
                    mma16(c[m][n][0], c[m][n][1], c[m][n][2], c[m][n][3], a0, a1, a2, a3, b[n][0], b[n][1]);
            }
        }

        // register epilogue: msg = (D2+b2)*C*xf[src] -> red into agg[dst]
        #pragma unroll
        for (int m = 0; m < 8; m++) {
            #pragma unroll
            for (int h = 0; h < 2; h++) {
                int el = m * 16 + g + h * 8;
                float Cv = sC[el];
                const float* xfp = g_xf + (size_t)sS[el] * 128;
                float* agp = g_agg + (size_t)sD[el] * 128;
                #pragma unroll
                for (int n = 0; n < 2; n++) {
                    int col = n0 + n * 8 + 2 * t4;
                    float2 x = *(const float2*)(xfp + col);
                    float v0 = (c[m][n][2 * h]     + b2s[col])     * Cv * x.x;
                    float v1 = (c[m][n][2 * h + 1] + b2s[col + 1]) * Cv * x.y;
                    red2(agp + col, v0, v1);
                }
            }
        }
        __syncthreads();
    }
}

// ---------------- readout ----------------------------------------------------
__global__ __launch_bounds__(128) void readout_kernel(const float* __restrict__ w1,
                                                      const float* __restrict__ b1,
                                                      const float* __restrict__ w2,
                                                      const float* __restrict__ b2v,
                                                      const int* __restrict__ batch,
                                                      float* __restrict__ out) {
    __shared__ float w1s[128 * 64];
    __shared__ float w2s2[64];
    __shared__ float hs[2][128];
    __shared__ float red[2][64];
    int tid = threadIdx.x;
    for (int i = tid; i < 128 * 64; i += 128) w1s[i] = w1[i];
    if (tid < 64) w2s2[tid] = w2[tid];
    __syncthreads();
    int half = tid >> 6, c = tid & 63;
    float b1r = b1[c], b2r = b2v[0];
    const int npairs = N_NODES / 2;
    for (int pair = blockIdx.x; pair < npairs; pair += gridDim.x) {
        for (int i = tid; i < 256; i += 128)
            hs[i >> 7][i & 127] = g_h[(size_t)(pair * 2 + (i >> 7)) * 128 + (i & 127)];
        __syncthreads();
        float acc = b1r;
        #pragma unroll 4
        for (int k = 0; k < 128; k++) acc += hs[half][k] * w1s[k * 64 + c];
        red[half][c] = sspf(acc) * w2s2[c];
        __syncthreads();
        if (c < 32) {
            float v = red[half][c] + red[half][c + 32];
            #pragma unroll
            for (int off = 16; off >= 1; off >>= 1) v += __shfl_down_sync(0xffffffffu, v, off);
            if (c == 0) atomicAdd(&out[batch[pair * 2 + half]], v + b2r);
        }
        __syncthreads();
    }
}

// ---------------- launch ------------------------------------------------------
extern "C" void kernel_launch(void* const* d_in, const int* in_sizes, int n_in,
                              void* d_out, int out_size) {
    const int*   z       = (const int*)d_in[0];
    const float* pos     = (const float*)d_in[1];
    const int*   ei      = (const int*)d_in[2];
    const int*   batch   = (const int*)d_in[3];
    const float* emb     = (const float*)d_in[4];
    const float* mlp_w1  = (const float*)d_in[5];
    const float* mlp_b1  = (const float*)d_in[6];
    const float* mlp_w2  = (const float*)d_in[7];
    const float* mlp_b2  = (const float*)d_in[8];
    const float* conv1_w = (const float*)d_in[9];
    const float* conv2_w = (const float*)d_in[10];
    const float* conv2_b = (const float*)d_in[11];
    const float* lin_w   = (const float*)d_in[12];
    const float* lin_b   = (const float*)d_in[13];
    const float* out1_w  = (const float*)d_in[14];
    const float* out1_b  = (const float*)d_in[15];
    const float* out2_w  = (const float*)d_in[16];
    const float* out2_b  = (const float*)d_in[17];

    const int CONV1_SMEM = (64 + 128) * SA * 4;                        // 101376
    const int GEMM2_SMEM = ((64 + 128) * SA + 256) * 4;                // 102400
    const int EDGE_SMEM  = (2 * 128 * W1S + 2 * 128 * W2S + 640) * 4;  // 109056
    cudaFuncSetAttribute(mm_conv1, cudaFuncAttributeMaxDynamicSharedMemorySize, CONV1_SMEM);
    cudaFuncSetAttribute(mm_gemm2, cudaFuncAttributeMaxDynamicSharedMemorySize, GEMM2_SMEM);
    cudaFuncSetAttribute(edge_mm, cudaFuncAttributeMaxDynamicSharedMemorySize, EDGE_SMEM);

    float *hP, *xfP, *aggP;
    cudaGetSymbolAddress((void**)&hP, g_h);
    cudaGetSymbolAddress((void**)&xfP, g_xf);
    cudaGetSymbolAddress((void**)&aggP, g_agg);

    detect_kernel<<<1, 32>>>(ei);
    prep_kernel<<<(E_EDGES + 255) / 256, 256>>>(ei, pos);
    embed_kernel<<<(N_NODES * 128 + 255) / 256, 256>>>(z, emb);

    const int gg = (N_NODES + 63) / 64;   // 782
    for (int l = 0; l < 3; l++) {
        mm_conv1<<<gg, 256, CONV1_SMEM>>>(hP, conv1_w + (size_t)l * 16384, xfP);
        cudaMemsetAsync(aggP, 0, (size_t)N_NODES * 128 * sizeof(float));
        edge_mm<<<296, 256, EDGE_SMEM>>>(mlp_w1 + (size_t)l * NG * 128,
                                         mlp_b1 + (size_t)l * 128,
                                         mlp_w2 + (size_t)l * 16384,
                                         mlp_b2 + (size_t)l * 128);
        mm_gemm2<<<gg, 256, GEMM2_SMEM>>>(aggP, conv2_w + (size_t)l * 16384,
                                          conv2_b + (size_t)l * 128,
                                          lin_w + (size_t)l * 16384,
                                          lin_b + (size_t)l * 128, hP);
    }

    cudaMemsetAsync(d_out, 0, NGRAPHS * sizeof(float));
    readout_kernel<<<1024, 128>>>(out1_w, out1_b, out2_w, out2_b, batch, (float*)d_out);
}